// round 3
// baseline (speedup 1.0000x reference)
#include <cuda_runtime.h>

// Problem constants (fixed by the reference module)
#define M_COUNT 20
#define R_COUNT 20
#define BATCH   400
#define STEPF   1e-4f

#define ONE_LANE 20            // lane holding constant 1.0f (pads single-substrate rate)
#define FULLMASK 0xFFFFFFFFu

// ---------------------------------------------------------------------------
// Kernel 1: warp-per-sample reaction integration, state in registers.
// Lane m (< 20) holds x[m]; lane 20 holds 1.0f. Dynamic substrate indexing is
// done with __shfl_sync. Update: every lane does xv += coef[r]*rate, where
// coef = STEP*(prod-sub) per lane (0 for untouched lanes -> exact identity).
// All metadata (i0/i1 uniform ints, 20 coefs) lives in registers (full unroll).
// ---------------------------------------------------------------------------
__global__ void __launch_bounds__(32)
sim_kernel(const float* __restrict__ x_in,
           const float* __restrict__ sub,
           const float* __restrict__ prd,
           const int*   __restrict__ niters,
           float*       __restrict__ x_out)
{
    const int lane = threadIdx.x;
    const int s    = blockIdx.x;            // one warp (block) per sample

    // --- build reaction metadata in registers ---
    float coef[R_COUNT];
    int   i0[R_COUNT], i1[R_COUNT];
    #pragma unroll
    for (int r = 0; r < R_COUNT; ++r) {
        float sv = 0.0f, pv = 0.0f;
        if (lane < M_COUNT) {
            sv = sub[r * M_COUNT + lane];
            pv = prd[r * M_COUNT + lane];
        }
        coef[r] = (pv - sv) * STEPF;        // 0 for lanes >= 20
        unsigned mask = __ballot_sync(FULLMASK, sv != 0.0f);
        if (mask) {
            i0[r] = __ffs(mask) - 1;
            unsigned m2 = mask & (mask - 1);
            i1[r] = m2 ? (__ffs(m2) - 1) : ONE_LANE;   // single substrate -> pad with 1.0
        } else {
            i0[r] = ONE_LANE;               // empty row -> rate = 1.0 (matches prod(x^0))
            i1[r] = ONE_LANE;
        }
    }

    // --- state ---
    float xv;
    if (lane < M_COUNT)       xv = x_in[s * M_COUNT + lane];
    else if (lane == ONE_LANE) xv = 1.0f;
    else                      xv = 0.0f;

    // Reference freezes a sample once i >= niter, so running exactly niter
    // full iterations is identical.
    const int n = niters[s];
    for (int it = 0; it < n; ++it) {
        #pragma unroll
        for (int r = 0; r < R_COUNT; ++r) {
            const float v0   = __shfl_sync(FULLMASK, xv, i0[r]);
            const float v1   = __shfl_sync(FULLMASK, xv, i1[r]);
            const float rate = v0 * v1;                 // law of mass action
            xv = fmaf(coef[r], rate, xv);               // sparse update, exact for coef=0
        }
    }

    if (lane < M_COUNT) x_out[s * M_COUNT + lane] = xv;
}

// ---------------------------------------------------------------------------
// Kernel 2: correlation matrix, one block per output ROW (20 blocks).
// Each block stages the full [400,20] tile in shared, redundantly computes all
// means and inverse norms (cheap), then its own centered-Gram row. No atomics,
// no cross-block deps, deterministic.
// ---------------------------------------------------------------------------
#define CB_THREADS 320          // 20 columns x 16 batch-chunks of 25

__global__ void __launch_bounds__(CB_THREADS)
corr_kernel(const float* __restrict__ xg, float* __restrict__ cout)
{
    __shared__ float xs[BATCH * M_COUNT];   // 32000 B
    __shared__ float ps[CB_THREADS];
    __shared__ float mean_s[M_COUNT];
    __shared__ float rn_s[M_COUNT];

    const int t = threadIdx.x;
    const int i = blockIdx.x;               // output row

    for (int k = t; k < BATCH * M_COUNT; k += CB_THREADS) xs[k] = xg[k];
    __syncthreads();

    const int j  = t / 16;                  // column 0..19
    const int ch = t % 16;                  // batch chunk 0..15 (25 samples each)
    const int b0 = ch * 25;

    // column means
    {
        float s = 0.0f;
        #pragma unroll 5
        for (int b = b0; b < b0 + 25; ++b) s += xs[b * M_COUNT + j];
        ps[t] = s;
    }
    __syncthreads();
    if (t < M_COUNT) {
        float s = 0.0f;
        #pragma unroll
        for (int c = 0; c < 16; ++c) s += ps[t * 16 + c];
        mean_s[t] = s * (1.0f / (float)BATCH);
    }
    __syncthreads();

    // column inverse norms (of centered columns)
    {
        const float mj = mean_s[j];
        float s = 0.0f;
        #pragma unroll 5
        for (int b = b0; b < b0 + 25; ++b) {
            const float v = xs[b * M_COUNT + j] - mj;
            s = fmaf(v, v, s);
        }
        ps[t] = s;
    }
    __syncthreads();
    if (t < M_COUNT) {
        float s = 0.0f;
        #pragma unroll
        for (int c = 0; c < 16; ++c) s += ps[t * 16 + c];
        rn_s[t] = rsqrtf(s);
    }
    __syncthreads();

    // row i of the centered Gram, scaled
    {
        const float mi = mean_s[i];
        const float mj = mean_s[j];
        float s = 0.0f;
        #pragma unroll 5
        for (int b = b0; b < b0 + 25; ++b) {
            const float vi = xs[b * M_COUNT + i] - mi;
            const float vj = xs[b * M_COUNT + j] - mj;
            s = fmaf(vi, vj, s);
        }
        ps[t] = s;
    }
    __syncthreads();
    if (t < M_COUNT) {
        float s = 0.0f;
        #pragma unroll
        for (int c = 0; c < 16; ++c) s += ps[t * 16 + c];
        cout[i * M_COUNT + t] = s * rn_s[i] * rn_s[t];
    }
}

// ---------------------------------------------------------------------------
// Launch. Inputs (metadata order): x[8000] f32, sub[400] f32, prod[400] f32,
// iterations_for_sample[400] i32. Output: x (8000 f32) then c (400 f32).
// Graph-capturable: two plain launches, no allocs, no syncs.
// ---------------------------------------------------------------------------
extern "C" void kernel_launch(void* const* d_in, const int* in_sizes, int n_in,
                              void* d_out, int out_size)
{
    const float* x   = (const float*)d_in[0];
    const float* sub = (const float*)d_in[1];
    const float* prd = (const float*)d_in[2];
    const int*   it  = (const int*)  d_in[3];
    float* out = (float*)d_out;

    sim_kernel<<<BATCH, 32>>>(x, sub, prd, it, out);
    corr_kernel<<<M_COUNT, CB_THREADS>>>(out, out + BATCH * M_COUNT);
}

// round 4
// speedup vs baseline: 1.0037x; 1.0037x over previous
#include <cuda_runtime.h>

// Problem constants (fixed by the reference module)
#define M_COUNT 20
#define R_COUNT 20
#define BATCH   400
#define STEPF   1e-4f

#define ONE_LANE 20            // lane holding constant 1.0f (pads single-substrate rate)
#define FULLMASK 0xFFFFFFFFu

// ---------------------------------------------------------------------------
// Kernel 1: warp-per-sample reaction integration, state in registers.
// Lane m (< 20) holds x[m]; lane 20 holds 1.0f. Dynamic substrate indexing is
// done with __shfl_sync. Update: every lane does xv += coef[r]*rate, where
// coef = STEP*(prod-sub) per lane (0 for untouched lanes -> exact identity).
// All metadata (i0/i1 uniform ints, 20 coefs) lives in registers (full unroll).
// ---------------------------------------------------------------------------
__global__ void __launch_bounds__(32)
sim_kernel(const float* __restrict__ x_in,
           const float* __restrict__ sub,
           const float* __restrict__ prd,
           const int*   __restrict__ niters,
           float*       __restrict__ x_out)
{
    const int lane = threadIdx.x;
    const int s    = blockIdx.x;            // one warp (block) per sample

    // --- build reaction metadata in registers ---
    float coef[R_COUNT];
    int   i0[R_COUNT], i1[R_COUNT];
    #pragma unroll
    for (int r = 0; r < R_COUNT; ++r) {
        float sv = 0.0f, pv = 0.0f;
        if (lane < M_COUNT) {
            sv = sub[r * M_COUNT + lane];
            pv = prd[r * M_COUNT + lane];
        }
        coef[r] = (pv - sv) * STEPF;        // 0 for lanes >= 20
        unsigned mask = __ballot_sync(FULLMASK, sv != 0.0f);
        if (mask) {
            i0[r] = __ffs(mask) - 1;
            unsigned m2 = mask & (mask - 1);
            i1[r] = m2 ? (__ffs(m2) - 1) : ONE_LANE;   // single substrate -> pad with 1.0
        } else {
            i0[r] = ONE_LANE;               // empty row -> rate = 1.0 (matches prod(x^0))
            i1[r] = ONE_LANE;
        }
    }

    // --- state ---
    float xv;
    if (lane < M_COUNT)       xv = x_in[s * M_COUNT + lane];
    else if (lane == ONE_LANE) xv = 1.0f;
    else                      xv = 0.0f;

    // Reference freezes a sample once i >= niter, so running exactly niter
    // full iterations is identical.
    const int n = niters[s];
    for (int it = 0; it < n; ++it) {
        #pragma unroll
        for (int r = 0; r < R_COUNT; ++r) {
            const float v0   = __shfl_sync(FULLMASK, xv, i0[r]);
            const float v1   = __shfl_sync(FULLMASK, xv, i1[r]);
            const float rate = v0 * v1;                 // law of mass action
            xv = fmaf(coef[r], rate, xv);               // sparse update, exact for coef=0
        }
    }

    if (lane < M_COUNT) x_out[s * M_COUNT + lane] = xv;
}

// ---------------------------------------------------------------------------
// Kernel 2: correlation matrix, one block per output ROW (20 blocks).
// Each block stages the full [400,20] tile in shared, redundantly computes all
// means and inverse norms (cheap), then its own centered-Gram row. No atomics,
// no cross-block deps, deterministic.
// ---------------------------------------------------------------------------
#define CB_THREADS 320          // 20 columns x 16 batch-chunks of 25

__global__ void __launch_bounds__(CB_THREADS)
corr_kernel(const float* __restrict__ xg, float* __restrict__ cout)
{
    __shared__ float xs[BATCH * M_COUNT];   // 32000 B
    __shared__ float ps[CB_THREADS];
    __shared__ float mean_s[M_COUNT];
    __shared__ float rn_s[M_COUNT];

    const int t = threadIdx.x;
    const int i = blockIdx.x;               // output row

    for (int k = t; k < BATCH * M_COUNT; k += CB_THREADS) xs[k] = xg[k];
    __syncthreads();

    const int j  = t / 16;                  // column 0..19
    const int ch = t % 16;                  // batch chunk 0..15 (25 samples each)
    const int b0 = ch * 25;

    // column means
    {
        float s = 0.0f;
        #pragma unroll 5
        for (int b = b0; b < b0 + 25; ++b) s += xs[b * M_COUNT + j];
        ps[t] = s;
    }
    __syncthreads();
    if (t < M_COUNT) {
        float s = 0.0f;
        #pragma unroll
        for (int c = 0; c < 16; ++c) s += ps[t * 16 + c];
        mean_s[t] = s * (1.0f / (float)BATCH);
    }
    __syncthreads();

    // column inverse norms (of centered columns)
    {
        const float mj = mean_s[j];
        float s = 0.0f;
        #pragma unroll 5
        for (int b = b0; b < b0 + 25; ++b) {
            const float v = xs[b * M_COUNT + j] - mj;
            s = fmaf(v, v, s);
        }
        ps[t] = s;
    }
    __syncthreads();
    if (t < M_COUNT) {
        float s = 0.0f;
        #pragma unroll
        for (int c = 0; c < 16; ++c) s += ps[t * 16 + c];
        rn_s[t] = rsqrtf(s);
    }
    __syncthreads();

    // row i of the centered Gram, scaled
    {
        const float mi = mean_s[i];
        const float mj = mean_s[j];
        float s = 0.0f;
        #pragma unroll 5
        for (int b = b0; b < b0 + 25; ++b) {
            const float vi = xs[b * M_COUNT + i] - mi;
            const float vj = xs[b * M_COUNT + j] - mj;
            s = fmaf(vi, vj, s);
        }
        ps[t] = s;
    }
    __syncthreads();
    if (t < M_COUNT) {
        float s = 0.0f;
        #pragma unroll
        for (int c = 0; c < 16; ++c) s += ps[t * 16 + c];
        cout[i * M_COUNT + t] = s * rn_s[i] * rn_s[t];
    }
}

// ---------------------------------------------------------------------------
// Launch. Inputs (metadata order): x[8000] f32, sub[400] f32, prod[400] f32,
// iterations_for_sample[400] i32. Output: x (8000 f32) then c (400 f32).
// Graph-capturable: two plain launches, no allocs, no syncs.
// ---------------------------------------------------------------------------
extern "C" void kernel_launch(void* const* d_in, const int* in_sizes, int n_in,
                              void* d_out, int out_size)
{
    const float* x   = (const float*)d_in[0];
    const float* sub = (const float*)d_in[1];
    const float* prd = (const float*)d_in[2];
    const int*   it  = (const int*)  d_in[3];
    float* out = (float*)d_out;

    sim_kernel<<<BATCH, 32>>>(x, sub, prd, it, out);
    corr_kernel<<<M_COUNT, CB_THREADS>>>(out, out + BATCH * M_COUNT);
}